// round 1
// baseline (speedup 1.0000x reference)
#include <cuda_runtime.h>
#include <math_constants.h>
#include <cstdint>

// Problem constants (fixed shapes for this dataset entry)
constexpr int N_NODES = 50000;
constexpr int DIM     = 256;    // IN == OUT == 256
constexpr int KSEL    = 32;
constexpr int NE      = 800000;

// Scratch (__device__ globals: allocation-free rule)
__device__ float g_neigh[(size_t)N_NODES * DIM];   // feat @ W_neigh^T + b
__device__ float g_vals[(size_t)N_NODES * KSEL];   // top-k values (sparse)
__device__ int   g_cols[(size_t)N_NODES * KSEL];   // top-k column indices

// ---------------------------------------------------------------------------
// Kernel 1: fused dual GEMM.
// C = feat @ [W_self; W_neigh]^T  -> [N, 512]
// cols [0,256)   -> d_out (h_self)
// cols [256,512) -> g_neigh (+ bias)
// Tiling: BM=128, BN=128, BK=16, 256 threads, 8x8 per thread.
// Each block's BN=128 column range lies entirely within one weight matrix.
// ---------------------------------------------------------------------------
#define BM 128
#define BN 128
#define BK 16
#define TM 8
#define TN 8

__global__ __launch_bounds__(256, 2)
void gemm_dual_kernel(const float* __restrict__ feat,
                      const float* __restrict__ Wself,
                      const float* __restrict__ Wneigh,
                      const float* __restrict__ bneigh,
                      float* __restrict__ out, int n)
{
    __shared__ float As[BK][BM];
    __shared__ float Bs[BK][BN];

    const int bn = blockIdx.x;            // 0..3 (512/128)
    const int bm = blockIdx.y;
    const int row0 = bm * BM;
    const int n0 = bn * BN;
    const bool is_neigh = (n0 >= DIM);
    const float* __restrict__ W =
        is_neigh ? (Wneigh + (size_t)(n0 - DIM) * DIM)
                 : (Wself  + (size_t)n0 * DIM);

    const int tid = threadIdx.x;
    const int tx = tid & 15;   // n direction
    const int ty = tid >> 4;   // m direction

    float acc[TM][TN] = {};

    for (int kt = 0; kt < DIM; kt += BK) {
        // Load A tile: 128 rows x 16 k (512 float4, 2 per thread), transpose into As[k][m]
        #pragma unroll
        for (int i = 0; i < 2; i++) {
            int id = tid * 2 + i;
            int ar = id >> 2;            // 0..127
            int ak = (id & 3) << 2;      // 0,4,8,12
            int grow = row0 + ar;
            float4 v = make_float4(0.f, 0.f, 0.f, 0.f);
            if (grow < n)
                v = *(const float4*)(feat + (size_t)grow * DIM + kt + ak);
            As[ak + 0][ar] = v.x;
            As[ak + 1][ar] = v.y;
            As[ak + 2][ar] = v.z;
            As[ak + 3][ar] = v.w;
        }
        // Load B tile: 128 out-cols x 16 k, transpose into Bs[k][nn]
        #pragma unroll
        for (int i = 0; i < 2; i++) {
            int id = tid * 2 + i;
            int br = id >> 2;
            int bk = (id & 3) << 2;
            float4 v = *(const float4*)(W + (size_t)br * DIM + kt + bk);
            Bs[bk + 0][br] = v.x;
            Bs[bk + 1][br] = v.y;
            Bs[bk + 2][br] = v.z;
            Bs[bk + 3][br] = v.w;
        }
        __syncthreads();

        #pragma unroll
        for (int k = 0; k < BK; k++) {
            float a[TM], b[TN];
            float4 a0 = *(const float4*)&As[k][ty * TM];
            float4 a1 = *(const float4*)&As[k][ty * TM + 4];
            float4 b0 = *(const float4*)&Bs[k][tx * TN];
            float4 b1 = *(const float4*)&Bs[k][tx * TN + 4];
            a[0]=a0.x; a[1]=a0.y; a[2]=a0.z; a[3]=a0.w;
            a[4]=a1.x; a[5]=a1.y; a[6]=a1.z; a[7]=a1.w;
            b[0]=b0.x; b[1]=b0.y; b[2]=b0.z; b[3]=b0.w;
            b[4]=b1.x; b[5]=b1.y; b[6]=b1.z; b[7]=b1.w;
            #pragma unroll
            for (int i = 0; i < TM; i++)
                #pragma unroll
                for (int j = 0; j < TN; j++)
                    acc[i][j] += a[i] * b[j];
        }
        __syncthreads();
    }

    // Epilogue
    float bias[TN];
    #pragma unroll
    for (int j = 0; j < TN; j++)
        bias[j] = is_neigh ? bneigh[(n0 - DIM) + tx * TN + j] : 0.f;

    float* __restrict__ dst = is_neigh ? (g_neigh + (n0 - DIM)) : (out + n0);

    #pragma unroll
    for (int i = 0; i < TM; i++) {
        int grow = row0 + ty * TM + i;
        if (grow >= n) break;
        float* p = dst + (size_t)grow * DIM + tx * TN;
        float4 v0 = make_float4(acc[i][0] + bias[0], acc[i][1] + bias[1],
                                acc[i][2] + bias[2], acc[i][3] + bias[3]);
        float4 v1 = make_float4(acc[i][4] + bias[4], acc[i][5] + bias[5],
                                acc[i][6] + bias[6], acc[i][7] + bias[7]);
        *(float4*)(p)     = v0;
        *(float4*)(p + 4) = v1;
    }
}

// ---------------------------------------------------------------------------
// Kernel 2: per-row top-32 of 256 -> sparse (col, val) lists.
// One warp per row; iterative argmax with warp reduction (tie -> smaller col,
// matching jax.lax.top_k first-occurrence order).
// ---------------------------------------------------------------------------
__global__ __launch_bounds__(256)
void topk_kernel(int n)
{
    const int warp = threadIdx.x >> 5;
    const int lane = threadIdx.x & 31;
    const int row = blockIdx.x * 8 + warp;
    if (row >= n) return;

    const float* __restrict__ src = g_neigh + (size_t)row * DIM;
    float v[8];
    #pragma unroll
    for (int i = 0; i < 8; i++) v[i] = src[lane + i * 32];

    float myv = 0.f;
    int   myc = 0;

    #pragma unroll 1
    for (int s = 0; s < KSEL; s++) {
        // local argmax over this lane's 8 values (ties -> smaller index)
        float bv = v[0]; int bi = 0;
        #pragma unroll
        for (int i = 1; i < 8; i++)
            if (v[i] > bv) { bv = v[i]; bi = i; }
        int bc = lane + bi * 32;
        // warp argmax, tie-break on smaller column
        #pragma unroll
        for (int off = 16; off; off >>= 1) {
            float ov = __shfl_xor_sync(0xffffffffu, bv, off);
            int   oc = __shfl_xor_sync(0xffffffffu, bc, off);
            if (ov > bv || (ov == bv && oc < bc)) { bv = ov; bc = oc; }
        }
        // winning lane removes its element
        if (lane == (bc & 31)) v[bc >> 5] = -CUDART_INF_F;
        // lane s keeps result s
        if (lane == s) { myv = bv; myc = bc; }
    }

    g_vals[(size_t)row * KSEL + lane] = myv;
    g_cols[(size_t)row * KSEL + lane] = myc;
}

// ---------------------------------------------------------------------------
// Kernel 3: CSR SpMM over sparse top-k rows, accumulate onto h_self in d_out.
// One warp per destination row; 256-float smem accumulator per warp.
// Within one edge the 32 (col,val) pairs have distinct cols -> no atomics.
// ---------------------------------------------------------------------------
__global__ __launch_bounds__(256)
void spmm_kernel(const int* __restrict__ indices,
                 const int* __restrict__ indptr,
                 float* __restrict__ out, int n)
{
    __shared__ float acc[8][DIM];
    const int warp = threadIdx.x >> 5;
    const int lane = threadIdx.x & 31;
    const int row = blockIdx.x * 8 + warp;
    if (row >= n) return;

    float* a = acc[warp];
    #pragma unroll
    for (int i = 0; i < 8; i++) a[lane + i * 32] = 0.f;
    __syncwarp();

    const int s = indptr[row];
    const int e = indptr[row + 1];
    for (int j = s; j < e; j++) {
        int srcrow = indices[j];
        int   col = g_cols[(size_t)srcrow * KSEL + lane];
        float val = g_vals[(size_t)srcrow * KSEL + lane];
        a[col] += val;   // distinct cols across lanes for this edge
        __syncwarp();    // keep lanes in lockstep across edges
    }
    __syncwarp();

    #pragma unroll
    for (int i = 0; i < 8; i++) {
        int c = lane + i * 32;
        out[(size_t)row * DIM + c] += a[c];
    }
}

// ---------------------------------------------------------------------------
extern "C" void kernel_launch(void* const* d_in, const int* in_sizes, int n_in,
                              void* d_out, int out_size)
{
    const float* feat   = (const float*)d_in[0];
    const float* Wself  = (const float*)d_in[1];
    const float* Wneigh = (const float*)d_in[2];
    const float* bneigh = (const float*)d_in[3];
    const int*   indices = (const int*)d_in[4];
    const int*   indptr  = (const int*)d_in[5];
    float* out = (float*)d_out;

    const int n = in_sizes[0] / DIM;   // 50000

    // 1) fused dual GEMM: h_self -> out, feat_neigh+bias -> g_neigh
    dim3 ggrid(2 * DIM / BN, (n + BM - 1) / BM);
    gemm_dual_kernel<<<ggrid, 256>>>(feat, Wself, Wneigh, bneigh, out, n);

    // 2) top-k -> sparse lists
    int blocks_rows = (n + 7) / 8;
    topk_kernel<<<blocks_rows, 256>>>(n);

    // 3) SpMM accumulate onto h_self
    spmm_kernel<<<blocks_rows, 256>>>(indices, indptr, out, n);
}

// round 3
// speedup vs baseline: 2.0767x; 2.0767x over previous
#include <cuda_runtime.h>
#include <cuda_bf16.h>
#include <cstdint>

constexpr int N_NODES = 50000;
constexpr int DIM     = 256;   // IN == OUT
constexpr int KSEL    = 32;

// ---------------------------------------------------------------------------
// Device-global scratch (allocation-free rule)
// ---------------------------------------------------------------------------
__device__ float    g_neigh[(size_t)N_NODES * DIM];  // feat @ W_neigh^T + b
__device__ uint2    g_pair [(size_t)N_NODES * KSEL]; // packed {val_bits, col}
__device__ uint16_t g_ahi  [(size_t)N_NODES * DIM];  // feat hi (bf16 bits)
__device__ uint16_t g_alo  [(size_t)N_NODES * DIM];  // feat lo
__device__ uint16_t g_whi  [2 * DIM * DIM];          // [Wself;Wneigh] hi
__device__ uint16_t g_wlo  [2 * DIM * DIM];          // [Wself;Wneigh] lo

// ---------------------------------------------------------------------------
// helpers
// ---------------------------------------------------------------------------
__device__ __forceinline__ uint32_t smem_u32(const void* p) {
    uint32_t a;
    asm("{ .reg .u64 t; cvta.to.shared.u64 t, %1; cvt.u32.u64 %0, t; }"
        : "=r"(a) : "l"(p));
    return a;
}
__device__ __forceinline__ void cpa16(uint32_t dst, const void* src, bool ok) {
    asm volatile("cp.async.cg.shared.global [%0], [%1], 16, %2;"
                 :: "r"(dst), "l"(src), "r"(ok ? 16 : 0) : "memory");
}
__device__ __forceinline__ void cpa_commit() {
    asm volatile("cp.async.commit_group;" ::: "memory");
}
template <int N>
__device__ __forceinline__ void cpa_wait() {
    asm volatile("cp.async.wait_group %0;" :: "n"(N) : "memory");
}
__device__ __forceinline__ void ldsm4(uint32_t addr, uint32_t r[4]) {
    asm volatile("ldmatrix.sync.aligned.m8n8.x4.shared.b16 {%0,%1,%2,%3}, [%4];"
                 : "=r"(r[0]), "=r"(r[1]), "=r"(r[2]), "=r"(r[3]) : "r"(addr));
}
__device__ __forceinline__ void mma16816(float c[4], const uint32_t a[4],
                                         uint32_t b0, uint32_t b1) {
    asm volatile(
        "mma.sync.aligned.m16n8k16.row.col.f32.bf16.bf16.f32 "
        "{%0,%1,%2,%3},{%4,%5,%6,%7},{%8,%9},{%0,%1,%2,%3};"
        : "+f"(c[0]), "+f"(c[1]), "+f"(c[2]), "+f"(c[3])
        : "r"(a[0]), "r"(a[1]), "r"(a[2]), "r"(a[3]), "r"(b0), "r"(b1));
}

// ---------------------------------------------------------------------------
// Kernel 0: split fp32 -> bf16 hi/lo for feat and both weight matrices
// ---------------------------------------------------------------------------
__device__ __forceinline__ void split4(float4 v, uint2& hi, uint2& lo) {
    __nv_bfloat16 h0 = __float2bfloat16(v.x), h1 = __float2bfloat16(v.y);
    __nv_bfloat16 h2 = __float2bfloat16(v.z), h3 = __float2bfloat16(v.w);
    __nv_bfloat16 l0 = __float2bfloat16(v.x - __bfloat162float(h0));
    __nv_bfloat16 l1 = __float2bfloat16(v.y - __bfloat162float(h1));
    __nv_bfloat16 l2 = __float2bfloat16(v.z - __bfloat162float(h2));
    __nv_bfloat16 l3 = __float2bfloat16(v.w - __bfloat162float(h3));
    hi.x = (uint32_t)__bfloat16_as_ushort(h0) | ((uint32_t)__bfloat16_as_ushort(h1) << 16);
    hi.y = (uint32_t)__bfloat16_as_ushort(h2) | ((uint32_t)__bfloat16_as_ushort(h3) << 16);
    lo.x = (uint32_t)__bfloat16_as_ushort(l0) | ((uint32_t)__bfloat16_as_ushort(l1) << 16);
    lo.y = (uint32_t)__bfloat16_as_ushort(l2) | ((uint32_t)__bfloat16_as_ushort(l3) << 16);
}

__global__ __launch_bounds__(256)
void split_kernel(const float* __restrict__ feat,
                  const float* __restrict__ Wself,
                  const float* __restrict__ Wneigh, int n)
{
    size_t nA4 = (size_t)n * DIM / 4;
    size_t nW4 = (size_t)2 * DIM * DIM / 4;   // 32768
    size_t tot = nA4 + nW4;
    for (size_t i = (size_t)blockIdx.x * blockDim.x + threadIdx.x; i < tot;
         i += (size_t)gridDim.x * blockDim.x) {
        float4 v; uint2 *hd, *ld;
        if (i < nA4) {
            v = ((const float4*)feat)[i];
            hd = (uint2*)g_ahi + i; ld = (uint2*)g_alo + i;
        } else {
            size_t j = i - nA4;
            const float* W = (j < 16384) ? Wself : Wneigh;
            size_t jj = (j < 16384) ? j : j - 16384;
            v = ((const float4*)W)[jj];
            hd = (uint2*)g_whi + j; ld = (uint2*)g_wlo + j;
        }
        uint2 hi, lo; split4(v, hi, lo);
        *hd = hi; *ld = lo;
    }
}

// ---------------------------------------------------------------------------
// Kernel 1: HMMA (mma.sync bf16) split GEMM.
// C = feat @ [W_self; W_neigh]^T -> [N, 512]; grid (4, ceil(n/128)).
// CTA tile 128x128xK256, BK=32, 8 warps (4m x 2n), warp tile 32x64.
// acc += Ahi*Bhi + Ahi*Blo + Alo*Bhi  (fp32 accumulate; lo*lo dropped ~2^-18)
// ---------------------------------------------------------------------------
constexpr int RS = 40;                           // smem row stride (bf16 elems)
constexpr int TILE_B = 128 * RS * 2;             // 10240 bytes per array
constexpr int STAGE_B = 4 * TILE_B;              // Ahi,Alo,Bhi,Blo
constexpr int GEMM_SMEM = 2 * STAGE_B;           // 81920

__device__ __forceinline__ void load_stage(uint32_t sb, int kt, int row0,
                                           int n0, int n, int tid)
{
    #pragma unroll
    for (int h = 0; h < 2; h++) {
        int c   = tid + h * 256;        // 0..511
        int row = c >> 2;
        int kc  = (c & 3) * 8;
        uint32_t soff = (uint32_t)(row * RS + kc) * 2;
        int gr = row0 + row;
        bool ok = gr < n;
        size_t aidx = ((size_t)(ok ? gr : 0)) * DIM + kt * 32 + kc;
        cpa16(sb + soff,              g_ahi + aidx, ok);
        cpa16(sb + TILE_B + soff,     g_alo + aidx, ok);
        size_t bidx = (size_t)(n0 + row) * DIM + kt * 32 + kc;
        cpa16(sb + 2 * TILE_B + soff, g_whi + bidx, true);
        cpa16(sb + 3 * TILE_B + soff, g_wlo + bidx, true);
    }
}

__global__ __launch_bounds__(256, 1)
void gemm_mma_kernel(const float* __restrict__ bneigh,
                     float* __restrict__ out, int n)
{
    extern __shared__ char smem[];
    const uint32_t sbase = smem_u32(smem);
    const int tid = threadIdx.x, lane = tid & 31, wid = tid >> 5;
    const int warp_m = wid & 3, warp_n = wid >> 2;
    const int n0 = blockIdx.x * 128;             // col in concat [0,512)
    const int row0 = blockIdx.y * 128;

    float acc[2][8][4] = {};

    load_stage(sbase, 0, row0, n0, n, tid);
    cpa_commit();

    #pragma unroll 1
    for (int kt = 0; kt < 8; kt++) {
        if (kt < 7) {
            load_stage(sbase + ((kt + 1) & 1) * STAGE_B, kt + 1, row0, n0, n, tid);
            cpa_commit();
            cpa_wait<1>();
        } else {
            cpa_wait<0>();
        }
        __syncthreads();

        const uint32_t st = sbase + (kt & 1) * STAGE_B;
        #pragma unroll
        for (int ks = 0; ks < 2; ks++) {
            const int k0 = ks * 16;
            uint32_t ahi[2][4], alo[2][4], bhi[4][4], blo[4][4];
            #pragma unroll
            for (int mf = 0; mf < 2; mf++) {
                uint32_t ra = st + (uint32_t)((warp_m * 32 + mf * 16 + (lane & 15)) * RS
                                              + k0 + (lane >> 4) * 8) * 2;
                ldsm4(ra, ahi[mf]);
                ldsm4(ra + TILE_B, alo[mf]);
            }
            #pragma unroll
            for (int ng = 0; ng < 4; ng++) {
                uint32_t rb = st + 2 * TILE_B
                    + (uint32_t)((warp_n * 64 + ng * 16 + (lane >> 4) * 8 + (lane & 7)) * RS
                                 + k0 + ((lane >> 3) & 1) * 8) * 2;
                ldsm4(rb, bhi[ng]);
                ldsm4(rb + TILE_B, blo[ng]);
            }
            #pragma unroll
            for (int mf = 0; mf < 2; mf++)
                #pragma unroll
                for (int nf = 0; nf < 8; nf++) {
                    uint32_t b0h = bhi[nf >> 1][(nf & 1) * 2];
                    uint32_t b1h = bhi[nf >> 1][(nf & 1) * 2 + 1];
                    uint32_t b0l = blo[nf >> 1][(nf & 1) * 2];
                    uint32_t b1l = blo[nf >> 1][(nf & 1) * 2 + 1];
                    mma16816(acc[mf][nf], ahi[mf], b0h, b1h);
                    mma16816(acc[mf][nf], ahi[mf], b0l, b1l);
                    mma16816(acc[mf][nf], alo[mf], b0h, b1h);
                }
        }
        __syncthreads();
    }

    // Epilogue
    const bool isneigh = (n0 >= DIM);
    float* __restrict__ dstb = isneigh ? g_neigh : out;
    #pragma unroll
    for (int nf = 0; nf < 8; nf++) {
        int col = (n0 & 255) + warp_n * 64 + nf * 8 + (lane & 3) * 2;
        float2 b = make_float2(0.f, 0.f);
        if (isneigh) b = *(const float2*)(bneigh + col);
        #pragma unroll
        for (int mf = 0; mf < 2; mf++) {
            int r0 = row0 + warp_m * 32 + mf * 16 + (lane >> 2);
            if (r0 < n) {
                float2 v = make_float2(acc[mf][nf][0] + b.x, acc[mf][nf][1] + b.y);
                *(float2*)(dstb + (size_t)r0 * DIM + col) = v;
            }
            int r1 = r0 + 8;
            if (r1 < n) {
                float2 v = make_float2(acc[mf][nf][2] + b.x, acc[mf][nf][3] + b.y);
                *(float2*)(dstb + (size_t)r1 * DIM + col) = v;
            }
        }
    }
}

// ---------------------------------------------------------------------------
// Kernel 2: per-row top-32 of 256 via radix select, packed sparse output.
// Tie handling: equal-to-threshold elements taken in ascending column order
// (matches jax.lax.top_k first-occurrence semantics).
// ---------------------------------------------------------------------------
__global__ __launch_bounds__(256)
void topk_kernel(int n)
{
    const int warp = threadIdx.x >> 5;
    const int lane = threadIdx.x & 31;
    const int row = blockIdx.x * 8 + warp;
    if (row >= n) return;

    const float* __restrict__ src = g_neigh + (size_t)row * DIM;
    float v[8]; uint32_t u[8];
    #pragma unroll
    for (int i = 0; i < 8; i++) {
        v[i] = src[lane + i * 32];
        uint32_t s = __float_as_uint(v[i]);
        u[i] = (s & 0x80000000u) ? ~s : (s | 0x80000000u);   // sortable key
    }

    // radix select: T = key of the 32nd largest element
    uint32_t T = 0;
    #pragma unroll
    for (int bit = 31; bit >= 0; bit--) {
        uint32_t cand = T | (1u << bit);
        int c = 0;
        #pragma unroll
        for (int i = 0; i < 8; i++) c += (u[i] >= cand);
        if (__reduce_add_sync(0xffffffffu, c) >= KSEL) T = cand;
    }

    int cgt = 0;
    #pragma unroll
    for (int i = 0; i < 8; i++) cgt += (u[i] > T);
    const int need = KSEL - __reduce_add_sync(0xffffffffu, cgt); // equals to take

    const uint32_t ltmask = (1u << lane) - 1u;
    int eqtaken = 0, base = 0;
    uint2* __restrict__ dst = g_pair + (size_t)row * KSEL;
    #pragma unroll
    for (int i = 0; i < 8; i++) {
        bool iseq = (u[i] == T);
        uint32_t beq = __ballot_sync(0xffffffffu, iseq);
        bool sel = (u[i] > T) ||
                   (iseq && (eqtaken + (int)__popc(beq & ltmask)) < need);
        eqtaken += __popc(beq);
        uint32_t bs = __ballot_sync(0xffffffffu, sel);
        if (sel) {
            int pos = base + __popc(bs & ltmask);
            dst[pos] = make_uint2(__float_as_uint(v[i]), (uint32_t)(lane + i * 32));
        }
        base += __popc(bs);
    }
}

// ---------------------------------------------------------------------------
// Kernel 3: CSR SpMM over packed sparse rows, accumulate onto h_self.
// One warp per dst row; 256-float smem accumulator; distinct cols per edge.
// ---------------------------------------------------------------------------
__global__ __launch_bounds__(256)
void spmm_kernel(const int* __restrict__ indices,
                 const int* __restrict__ indptr,
                 float* __restrict__ out, int n)
{
    __shared__ float acc[8][DIM];
    const int warp = threadIdx.x >> 5;
    const int lane = threadIdx.x & 31;
    const int row = blockIdx.x * 8 + warp;
    if (row >= n) return;

    float* a = acc[warp];
    #pragma unroll
    for (int i = 0; i < 8; i++) a[lane + i * 32] = 0.f;
    __syncwarp();

    const int s = indptr[row];
    const int e = indptr[row + 1];
    for (int j = s; j < e; j++) {
        int srcrow = indices[j];
        uint2 p = __ldg(&g_pair[(size_t)srcrow * KSEL + lane]);
        a[p.y] += __uint_as_float(p.x);
        __syncwarp();
    }

    #pragma unroll
    for (int i = 0; i < 8; i++) {
        int c = lane + i * 32;
        out[(size_t)row * DIM + c] += a[c];
    }
}

// ---------------------------------------------------------------------------
extern "C" void kernel_launch(void* const* d_in, const int* in_sizes, int n_in,
                              void* d_out, int out_size)
{
    const float* feat    = (const float*)d_in[0];
    const float* Wself   = (const float*)d_in[1];
    const float* Wneigh  = (const float*)d_in[2];
    const float* bneigh  = (const float*)d_in[3];
    const int*   indices = (const int*)d_in[4];
    const int*   indptr  = (const int*)d_in[5];
    float* out = (float*)d_out;

    const int n = in_sizes[0] / DIM;   // 50000

    static bool attr_set = false;
    if (!attr_set) {
        cudaFuncSetAttribute(gemm_mma_kernel,
                             cudaFuncAttributeMaxDynamicSharedMemorySize, GEMM_SMEM);
        attr_set = true;
    }

    // 0) fp32 -> bf16 hi/lo splits
    split_kernel<<<1024, 256>>>(feat, Wself, Wneigh, n);

    // 1) HMMA dual GEMM: h_self -> out, feat_neigh+bias -> g_neigh
    dim3 ggrid(4, (n + 127) / 128);
    gemm_mma_kernel<<<ggrid, 256, GEMM_SMEM>>>(bneigh, out, n);

    // 2) top-k -> packed sparse lists
    int blocks_rows = (n + 7) / 8;
    topk_kernel<<<blocks_rows, 256>>>(n);

    // 3) SpMM accumulate onto h_self
    spmm_kernel<<<blocks_rows, 256>>>(indices, indptr, out, n);
}